// round 6
// baseline (speedup 1.0000x reference)
#include <cuda_runtime.h>
#include <math.h>

#define BATCH 4
#define SEQ 8192
#define DIMN 1024
#define RCH 32                      /* rows per chunk (= per block) */
#define CPB (SEQ / RCH)             /* 256 chunks per batch */
#define NCHT (BATCH * CPB)          /* 1024 chunks total */
#define NSEG 16
#define SEGLEN (CPB / NSEG)         /* 16 */
#define LN_EPS_F 1e-5f
#define FULLMASK 0xffffffffu

// Scratch
__device__ float  g_S[NCHT * DIMN];          // chunk-final local z states (4 MB)
__device__ float  g_A[BATCH * NSEG * DIMN];  // segment aggregates (256 KB)
__device__ float2 g_stats[BATCH * SEQ];      // per-row (inv, nm) (256 KB)

__device__ __forceinline__ float sigm_om(const float* __restrict__ alphas, int head) {
    float al = __ldg(alphas + head);
    return 1.0f - 1.0f / (1.0f + expf(-al));      // om = 1 - sigmoid(alpha)
}
__device__ __forceinline__ float pow32(float om) {
    float t = om * om;  t = t * t;  t = t * t;  t = t * t;  t = t * t;   // om^32
    return t;
}

// ---------------- Pass 1: LN stats + local z-scan per chunk ----------------
// Block = 256 threads; thread owns channels tid*4..+3 (single head).
// 4 rows per barrier (batched reduce), double-buffered prefetch.
__global__ __launch_bounds__(256, 3) void mhesa_pass1(
    const float* __restrict__ x, const float* __restrict__ gamma,
    const float* __restrict__ beta, const float* __restrict__ alphas)
{
    __shared__ float red[2][4][16];   // [parity][row-in-group][0..7 sums | 8..15 sqs]

    const int tid = threadIdx.x;
    const int w = tid >> 5, lane = tid & 31;
    const int ch4 = tid * 4;
    const int chunk = blockIdx.x;               // 0..NCHT-1
    const int bat = chunk >> 8;                 // / CPB
    const int c = chunk & (CPB - 1);

    const float om = sigm_om(alphas, ch4 >> 7);
    const float4 g  = *(const float4*)(gamma + ch4);
    const float4 bb = *(const float4*)(beta + ch4);

    const size_t base = ((size_t)bat * SEQ + (size_t)c * RCH) * DIMN + ch4;
    const int row0 = bat * SEQ + c * RCH;

    float4 cur[4], nxt[4];
#pragma unroll
    for (int k = 0; k < 4; k++)
        cur[k] = __ldg((const float4*)(x + base + (size_t)k * DIMN));

    float4 z = make_float4(0.f, 0.f, 0.f, 0.f);

    for (int rb = 0; rb < RCH; rb += 4) {
        const int par = (rb >> 2) & 1;
        // prefetch next 4-row group (stays in flight across reduce + barrier)
        if (rb + 4 < RCH) {
#pragma unroll
            for (int k = 0; k < 4; k++)
                nxt[k] = __ldg((const float4*)(x + base + (size_t)(rb + 4 + k) * DIMN));
        }
        float sum[4], sq[4];
#pragma unroll
        for (int k = 0; k < 4; k++) {
            const float4 v = cur[k];
            sum[k] = (v.x + v.y) + (v.z + v.w);
            sq[k]  = fmaf(v.x, v.x, fmaf(v.y, v.y, fmaf(v.z, v.z, v.w * v.w)));
        }
#pragma unroll
        for (int off = 16; off; off >>= 1) {
#pragma unroll
            for (int k = 0; k < 4; k++) {
                sum[k] += __shfl_xor_sync(FULLMASK, sum[k], off);
                sq[k]  += __shfl_xor_sync(FULLMASK, sq[k],  off);
            }
        }
        if (lane == 0) {
#pragma unroll
            for (int k = 0; k < 4; k++) {
                red[par][k][w] = sum[k];
                red[par][k][8 + w] = sq[k];
            }
        }
        __syncthreads();
#pragma unroll
        for (int k = 0; k < 4; k++) {
            float S = 0.f, Q = 0.f;
#pragma unroll
            for (int j = 0; j < 8; j++) { S += red[par][k][j]; Q += red[par][k][8 + j]; }
            const float mean = S * (1.0f / (float)DIMN);
            const float var  = fmaf(Q, 1.0f / (float)DIMN, -mean * mean);
            const float inv  = rsqrtf(var + LN_EPS_F);
            const float nm   = -mean * inv;
            if (tid == k) g_stats[row0 + rb + k] = make_float2(inv, nm);
            const float4 v = cur[k];
            float4 u;
            u.x = fmaf(fmaf(v.x, inv, nm), g.x, bb.x);
            u.y = fmaf(fmaf(v.y, inv, nm), g.y, bb.y);
            u.z = fmaf(fmaf(v.z, inv, nm), g.z, bb.z);
            u.w = fmaf(fmaf(v.w, inv, nm), g.w, bb.w);
            z.x = fmaf(om, z.x, u.x);
            z.y = fmaf(om, z.y, u.y);
            z.z = fmaf(om, z.z, u.z);
            z.w = fmaf(om, z.w, u.w);
        }
#pragma unroll
        for (int k = 0; k < 4; k++) cur[k] = nxt[k];
    }
    *(float4*)(g_S + (size_t)chunk * DIMN + ch4) = z;
}

// ---------------- Carry phase A: segment aggregates ----------------
// A[b,seg] = sum_j omC^(SEGLEN-1-j) * S[b, seg*SEGLEN + j]
__global__ void mhesa_carryA(const float* __restrict__ alphas)
{
    const int t = blockIdx.x * 256 + threadIdx.x;       // 0..65535
    const int ch = t & (DIMN - 1);
    const int rest = t >> 10;                            // b*NSEG + seg
    const float omC = pow32(sigm_om(alphas, ch >> 7));
    const size_t base = (size_t)rest * SEGLEN * DIMN + ch;
    float s[SEGLEN];
#pragma unroll
    for (int j = 0; j < SEGLEN; j++) s[j] = g_S[base + (size_t)j * DIMN];
    float A = 0.f;
#pragma unroll
    for (int j = 0; j < SEGLEN; j++) A = fmaf(omC, A, s[j]);
    g_A[(size_t)rest * DIMN + ch] = A;
}

// ---------------- Pass 2: inline carry fold + pure stream ----------------
// Entry carry computed per block from g_A (segment prefix) + g_S (within segment).
__global__ __launch_bounds__(256, 4) void mhesa_pass2(
    const float* __restrict__ x, const float* __restrict__ gamma,
    const float* __restrict__ beta, const float* __restrict__ alphas,
    const float* __restrict__ paramD, float* __restrict__ out)
{
    const int tid = threadIdx.x;
    const int ch4 = tid * 4;
    const int chunk = NCHT - 1 - blockIdx.x;    // reverse: reuse pass1's L2 tail
    const int bat = chunk >> 8;
    const int c = chunk & (CPB - 1);
    const int seg = c >> 4, j = c & (SEGLEN - 1);

    const float om = sigm_om(alphas, ch4 >> 7);
    const float a = 1.0f - om;
    const float4 g  = *(const float4*)(gamma + ch4);
    const float4 bb = *(const float4*)(beta + ch4);
    const float4 d  = *(const float4*)(paramD + ch4);

    const size_t base = ((size_t)bat * SEQ + (size_t)c * RCH) * DIMN + ch4;
    const int row0 = bat * SEQ + c * RCH;

    // x prefetch first so it's in flight during the carry fold
    float4 buf[4];
#pragma unroll
    for (int k = 0; k < 4; k++)
        buf[k] = __ldg((const float4*)(x + base + (size_t)k * DIMN));

    // ---- inline entry-carry fold (all operands L2-resident) ----
    const float omC = pow32(om);
    float omSeg = omC; omSeg *= omSeg; omSeg *= omSeg;
    omSeg *= omSeg; omSeg *= omSeg;               // omC^16 = om^512
    float4 z = make_float4(0.f, 0.f, 0.f, 0.f);
    {
        const float* ap = g_A + ((size_t)bat * NSEG) * DIMN + ch4;
        for (int s2 = 0; s2 < seg; s2++) {
            const float4 A = __ldg((const float4*)(ap + (size_t)s2 * DIMN));
            z.x = fmaf(omSeg, z.x, A.x);
            z.y = fmaf(omSeg, z.y, A.y);
            z.z = fmaf(omSeg, z.z, A.z);
            z.w = fmaf(omSeg, z.w, A.w);
        }
        const float* sp = g_S + ((size_t)(bat * CPB + seg * SEGLEN)) * DIMN + ch4;
        for (int k = 0; k < j; k++) {
            const float4 s4 = __ldg((const float4*)(sp + (size_t)k * DIMN));
            z.x = fmaf(omC, z.x, s4.x);
            z.y = fmaf(omC, z.y, s4.y);
            z.z = fmaf(omC, z.z, s4.z);
            z.w = fmaf(omC, z.w, s4.w);
        }
    }

    // ---- stream ----
    for (int rb = 0; rb < RCH; rb += 4) {
#pragma unroll
        for (int k = 0; k < 4; k++) {
            const int r = rb + k;
            const float4 v = buf[k];
            if (r + 4 < RCH)
                buf[k] = __ldg((const float4*)(x + base + (size_t)(r + 4) * DIMN));
            const float2 st = __ldg(&g_stats[row0 + r]);   // (inv, nm), warp-broadcast
            const float inv = st.x, nm = st.y;
            float4 u;
            u.x = fmaf(fmaf(v.x, inv, nm), g.x, bb.x);
            u.y = fmaf(fmaf(v.y, inv, nm), g.y, bb.y);
            u.z = fmaf(fmaf(v.z, inv, nm), g.z, bb.z);
            u.w = fmaf(fmaf(v.w, inv, nm), g.w, bb.w);
            z.x = fmaf(om, z.x, u.x);
            z.y = fmaf(om, z.y, u.y);
            z.z = fmaf(om, z.z, u.z);
            z.w = fmaf(om, z.w, u.w);
            float4 o;
            o.x = fmaf(u.x, d.x, a * z.x);
            o.y = fmaf(u.y, d.y, a * z.y);
            o.z = fmaf(u.z, d.z, a * z.z);
            o.w = fmaf(u.w, d.w, a * z.w);
            __stcs((float4*)(out + base + (size_t)r * DIMN), o);
        }
    }
}

extern "C" void kernel_launch(void* const* d_in, const int* in_sizes, int n_in,
                              void* d_out, int out_size)
{
    const float* x      = (const float*)d_in[0];
    const float* gamma  = (const float*)d_in[1];
    const float* beta   = (const float*)d_in[2];
    const float* alphas = (const float*)d_in[3];
    const float* paramD = (const float*)d_in[4];
    float* out = (float*)d_out;

    mhesa_pass1<<<NCHT, 256>>>(x, gamma, beta, alphas);
    mhesa_carryA<<<(BATCH * NSEG * DIMN) / 256, 256>>>(alphas);
    mhesa_pass2<<<NCHT, 256>>>(x, gamma, beta, alphas, paramD, out);
}